// round 17
// baseline (speedup 1.0000x reference)
#include <cuda_runtime.h>
#include <cuda_fp16.h>
#include <cstdint>
#include <cstddef>

using h16 = __half;

constexpr int B_  = 4;
constexpr int DIM = 256;
constexpr int MID = 128;
constexpr int HH  = 128;
constexpr int WW  = 128;
constexpr int HW  = HH * WW;

// ------------------------- device scratch -------------------------
__device__ float g_p1[(size_t)B_ * MID * HW];
__device__ float g_p2[(size_t)B_ * MID * HW];
__device__ float g_t1[(size_t)B_ * DIM * HW];      // r
__device__ float g_scale[1024];
__device__ float g_bias[1024];

__device__ h16 g_xT_hi[(size_t)B_ * HW * DIM];
__device__ h16 g_xT_lo[(size_t)B_ * HW * DIM];
__device__ h16 g_sT_hi[(size_t)B_ * HW * MID];
__device__ h16 g_sT_lo[(size_t)B_ * HW * MID];
__device__ h16 g_rT_hi[(size_t)B_ * HW * DIM];
__device__ h16 g_rT_lo[(size_t)B_ * HW * DIM];

constexpr size_t WOFF_P1 = 0;
constexpr size_t WOFF_P2 = WOFF_P1 + (size_t)MID * DIM * 9;
constexpr size_t WOFF_C1 = WOFF_P2 + (size_t)MID * DIM * 9;
constexpr size_t WOFF_C2 = WOFF_C1 + (size_t)DIM * MID * 9;
constexpr size_t WOFF_P3 = WOFF_C2 + (size_t)DIM * DIM * 1;
constexpr size_t WTOT    = WOFF_P3 + (size_t)DIM * DIM * 9;
__device__ h16 g_w[WTOT];          // fp16, BN-scale folded

struct P5 { const float* p[5]; };

// ------------------------- helpers (sm_80+ generic) -------------------------
__device__ __forceinline__ uint32_t smem_u32(const void* p) {
    uint32_t a;
    asm("{ .reg .u64 t; cvta.to.shared.u64 t, %1; cvt.u32.u64 %0, t; }" : "=r"(a) : "l"(p));
    return a;
}
__device__ __forceinline__ void ldsm4(uint32_t addr, uint32_t* r) {
    asm volatile("ldmatrix.sync.aligned.m8n8.x4.shared.b16 {%0,%1,%2,%3}, [%4];"
                 : "=r"(r[0]), "=r"(r[1]), "=r"(r[2]), "=r"(r[3]) : "r"(addr));
}
__device__ __forceinline__ void mma16816(float* c, const uint32_t* a, uint32_t b0, uint32_t b1) {
    asm volatile("mma.sync.aligned.m16n8k16.row.col.f32.f16.f16.f32 "
                 "{%0,%1,%2,%3}, {%4,%5,%6,%7}, {%8,%9}, {%0,%1,%2,%3};"
                 : "+f"(c[0]), "+f"(c[1]), "+f"(c[2]), "+f"(c[3])
                 : "r"(a[0]), "r"(a[1]), "r"(a[2]), "r"(a[3]), "r"(b0), "r"(b1));
}
__device__ __forceinline__ void cpa16(uint32_t dst, const void* src) {
    asm volatile("cp.async.cg.shared.global [%0], [%1], 16;" :: "r"(dst), "l"(src) : "memory");
}
__device__ __forceinline__ void cpa_commit() { asm volatile("cp.async.commit_group;" ::: "memory"); }
__device__ __forceinline__ void cpa_wait0()  { asm volatile("cp.async.wait_group 0;" ::: "memory"); }

// ------------------------- merged prep kernels -------------------------
__global__ void bn_prep_all(P5 g, P5 b, P5 m, P5 v,
                            float* __restrict__ scale, float* __restrict__ bias)
{
    int i = blockIdx.x * 256 + threadIdx.x;     // 0..1023
    if (i >= 1024) return;
    int seg, off;
    if      (i < 128) { seg = 0; off = 0;   }
    else if (i < 256) { seg = 1; off = 128; }
    else if (i < 512) { seg = 2; off = 256; }
    else if (i < 768) { seg = 3; off = 512; }
    else              { seg = 4; off = 768; }
    int c = i - off;
    float s = g.p[seg][c] * rsqrtf(v.p[seg][c] + 1e-5f);
    scale[off + c] = s;
    bias[off + c]  = b.p[seg][c] - m.p[seg][c] * s;
}

__global__ void wsplit_all(P5 w, const float* __restrict__ scale, h16* __restrict__ wo)
{
    int i = blockIdx.x * 256 + threadIdx.x;     // 0..229375
    int seg, base, CIN, T, soff; size_t woff; int COUT;
    if      (i < 32768)  { seg = 0; base = 0;      COUT = 128; CIN = 256; T = 9; woff = WOFF_P1; soff = 0;   }
    else if (i < 65536)  { seg = 1; base = 32768;  COUT = 128; CIN = 256; T = 9; woff = WOFF_P2; soff = 128; }
    else if (i < 98304)  { seg = 2; base = 65536;  COUT = 256; CIN = 128; T = 9; woff = WOFF_C1; soff = 256; }
    else if (i < 163840) { seg = 3; base = 98304;  COUT = 256; CIN = 256; T = 1; woff = WOFF_C2; soff = 512; }
    else                 { seg = 4; base = 163840; COUT = 256; CIN = 256; T = 9; woff = WOFF_P3; soff = 768; }
    int j = i - base;
    int co = j / CIN, ci = j % CIN;
    float sc = scale[soff + co];
    const float* src = w.p[seg];
    for (int t = 0; t < T; t++)
        wo[woff + ((size_t)t * COUT + co) * CIN + ci] = __float2half(src[(size_t)j * T + t] * sc);
    (void)COUT;
}

// NCHW f32 -> NHWC fp16 hi/lo. grid (HW/32, C/32, B), block 256
__global__ void split_T(const float* __restrict__ in, h16* __restrict__ hi,
                        h16* __restrict__ lo, int C)
{
    __shared__ float t[32][33];
    int pt = blockIdx.x * 32, ct = blockIdx.y * 32, z = blockIdx.z;
    int tx = threadIdx.x & 31, ty = threadIdx.x >> 5;
#pragma unroll
    for (int j = 0; j < 32; j += 8)
        t[ty + j][tx] = in[((size_t)z * C + ct + ty + j) * HW + pt + tx];
    __syncthreads();
#pragma unroll
    for (int j = 0; j < 32; j += 8) {
        float v = t[tx][ty + j];
        h16 h = __float2half(v);
        size_t o = ((size_t)z * HW + pt + ty + j) * C + ct + tx;
        hi[o] = h;
        lo[o] = __float2half(v - __half2float(h));
    }
}

// ===================== generic 3x3 conv, CIN=256, full-row tile ============
// CTA: 128 couts x 128 pixels. 8 warps: 2(M) x 4(N), warp tile 64co x 32px.
// 128 B of ldsm traffic per mma (vs 192 before) -> smem no longer co-binding.
// B in 4-slot row ring prefetched 2 groups ahead; A ping-pong via cp.async.
template<bool DUAL>
__global__ __launch_bounds__(256, 1)
void conv3(const h16* __restrict__ xhi, const h16* __restrict__ xlo,
           const h16* __restrict__ w0, const h16* __restrict__ w1,
           const float* __restrict__ bias0, const float* __restrict__ bias1,
           float* __restrict__ out0, float* __restrict__ out1, int COUT)
{
    constexpr int CIN = 256;
    constexpr int SPX = 130, BPL = SPX * 128, SLOT = 2 * BPL;
    constexpr int ABASE = 4 * SLOT;            // 133120
    constexpr int ABUF  = 16384;
    constexpr int NG = 12;                     // 4 chunks x 3 rows

    extern __shared__ char sm[];
    const uint32_t su = smem_u32(sm);

    const int tid = threadIdx.x, wid = tid >> 5, lane = tid & 31;
    const int h  = blockIdx.x & 127, b = blockIdx.x >> 7;
    const int y  = blockIdx.y;
    const int co0 = DUAL ? 0 : (y << 7);
    const h16* wgt = (DUAL && y) ? w1 : w0;
    const float* bias = (DUAL && y) ? bias1 : bias0;
    float* out = (DUAL && y) ? out1 : out0;

    const int warpM = wid >> 2, warpN = wid & 3;   // 2 x 4
    const int mo = warpM * 64;

    float acc[4][4][4];
#pragma unroll
    for (int i = 0; i < 4; i++)
#pragma unroll
        for (int j = 0; j < 4; j++)
#pragma unroll
            for (int k = 0; k < 4; k++) acc[i][j][k] = 0.f;

    auto stage_A = [&](int tap, int ci0, int buf) {
#pragma unroll
        for (int it = 0; it < 4; it++) {
            int u = tid + it * 256;
            int chunk = u & 7, co = u >> 3;
            const h16* src = wgt + ((size_t)(tap * COUT + co0 + co)) * CIN + ci0 + chunk * 8;
            cpa16(su + ABASE + buf * ABUF + co * 128 + ((chunk ^ (co & 7)) << 4), src);
        }
        cpa_commit();
    };
    auto stage_Brow = [&](int plane, int c, int r, int slot) {
        const h16* basep = plane ? xlo : xhi;
        const int hr = h - 1 + r;
        for (int u = tid; u < SPX * 8; u += 256) {
            int chunk = u & 7, px = u >> 3;
            int gpx = px - 1;
            uint32_t doff = slot * SLOT + plane * BPL + px * 128 + ((chunk ^ (px & 7)) << 4);
            if ((unsigned)hr < (unsigned)HH && (unsigned)gpx < (unsigned)WW)
                cpa16(su + doff, basep + ((size_t)((b * HH + hr) * WW + gpx)) * CIN + c * 64 + chunk * 8);
            else
                *reinterpret_cast<uint4*>(sm + doff) = make_uint4(0, 0, 0, 0);
        }
        cpa_commit();
    };

    stage_Brow(0, 0, 0, 0); stage_Brow(1, 0, 0, 0);
    stage_Brow(0, 0, 1, 1); stage_Brow(1, 0, 1, 1);
    stage_A(0, 0, 0);
    cpa_wait0(); __syncthreads();

    int seq = 0;
    for (int gq = 0; gq < NG; gq++) {
        const int slot = gq & 3;
        const uint32_t bhB = su + slot * SLOT, blB = bhB + BPL;
        const int ng = gq + 2;
#pragma unroll 1
        for (int sl = 0; sl < 3; sl++, seq++) {
            const int nxt = seq + 1;
            if (nxt < 36) stage_A(nxt % 9, (nxt / 9) * 64, nxt & 1);
            if (ng < NG && sl < 2) stage_Brow(sl, ng / 3, ng % 3, ng & 3);

            const uint32_t Ab = su + ABASE + (seq & 1) * ABUF;
            const int sp0 = warpN * 32 + sl;
#pragma unroll
            for (int k = 0; k < 4; k++) {
                uint32_t ah[4][4];
#pragma unroll
                for (int mt = 0; mt < 4; mt++) {
                    int row = mo + mt * 16 + (lane & 15);
                    int ck  = k * 2 + (lane >> 4);
                    ldsm4(Ab + row * 128 + ((ck ^ (row & 7)) << 4), ah[mt]);
                }
#pragma unroll
                for (int np = 0; np < 2; np++) {
                    uint32_t bh[4], bl[4];
                    int px = sp0 + np * 16 + (lane & 7) + ((lane >> 4) << 3);
                    int ck = k * 2 + ((lane >> 3) & 1);
                    uint32_t off = px * 128 + ((ck ^ (px & 7)) << 4);
                    ldsm4(bhB + off, bh);
                    ldsm4(blB + off, bl);
#pragma unroll
                    for (int mt = 0; mt < 4; mt++)
#pragma unroll
                        for (int sb = 0; sb < 2; sb++) {
                            float* cc = acc[mt][np * 2 + sb];
                            mma16816(cc, ah[mt], bh[sb * 2], bh[sb * 2 + 1]);
                            mma16816(cc, ah[mt], bl[sb * 2], bl[sb * 2 + 1]);
                        }
                }
            }
            cpa_wait0(); __syncthreads();
        }
    }

    const int g = lane >> 2, q = lane & 3;
#pragma unroll
    for (int mt = 0; mt < 4; mt++)
#pragma unroll
        for (int half = 0; half < 2; half++) {
            const int co = co0 + mo + mt * 16 + g + half * 8;
            const float bi = bias[co];
            const size_t rowb = ((size_t)(b * COUT + co) * HH + h) * WW;
#pragma unroll
            for (int nt = 0; nt < 4; nt++) {
                const int px = warpN * 32 + nt * 8 + q * 2;
                float v0 = fmaxf(acc[mt][nt][half * 2 + 0] + bi, 0.f);
                float v1 = fmaxf(acc[mt][nt][half * 2 + 1] + bi, 0.f);
                *reinterpret_cast<float2*>(out + rowb + px) = make_float2(v0, v1);
            }
        }
}

// ===================== fused c1(3x3 over s) + c2(1x1 over x) ==============
__global__ __launch_bounds__(256, 1)
void conv_c1c2(const h16* __restrict__ shi, const h16* __restrict__ slo,
               const h16* __restrict__ xhi, const h16* __restrict__ xlo,
               const h16* __restrict__ w1, const h16* __restrict__ w2,
               const float* __restrict__ b1, const float* __restrict__ b2,
               float* __restrict__ out)
{
    constexpr int COUT = 256;
    constexpr int SPX = 130, BPL = SPX * 128, SLOT = 2 * BPL;
    constexpr int ABASE = 4 * SLOT;
    constexpr int ABUF  = 16384;
    constexpr int NG1 = 6;

    extern __shared__ char sm[];
    const uint32_t su = smem_u32(sm);

    const int tid = threadIdx.x, wid = tid >> 5, lane = tid & 31;
    const int h  = blockIdx.x & 127, b = blockIdx.x >> 7;
    const int co0 = blockIdx.y << 7;
    const int warpM = wid >> 2, warpN = wid & 3;
    const int mo = warpM * 64;

    float acc[4][4][4];
#pragma unroll
    for (int i = 0; i < 4; i++)
#pragma unroll
        for (int j = 0; j < 4; j++)
#pragma unroll
            for (int k = 0; k < 4; k++) acc[i][j][k] = 0.f;

    // seq 0..17: c1 (tap=seq%9, chunk=seq/9, CIN=128); seq 18..21: c2 (chunk=seq-18, CIN=256)
    auto stage_A = [&](int seq, int buf) {
#pragma unroll
        for (int it = 0; it < 4; it++) {
            int u = tid + it * 256;
            int chunk = u & 7, co = u >> 3;
            const h16* src;
            if (seq < 18) {
                int tap = seq % 9, ch = seq / 9;
                src = w1 + ((size_t)(tap * COUT + co0 + co)) * 128 + ch * 64 + chunk * 8;
            } else {
                int ch = seq - 18;
                src = w2 + ((size_t)(co0 + co)) * 256 + ch * 64 + chunk * 8;
            }
            cpa16(su + ABASE + buf * ABUF + co * 128 + ((chunk ^ (co & 7)) << 4), src);
        }
        cpa_commit();
    };
    auto stage_Brow = [&](int plane, int c, int r, int slot) {   // s rows, CIN=128
        const h16* basep = plane ? slo : shi;
        const int hr = h - 1 + r;
        for (int u = tid; u < SPX * 8; u += 256) {
            int chunk = u & 7, px = u >> 3;
            int gpx = px - 1;
            uint32_t doff = slot * SLOT + plane * BPL + px * 128 + ((chunk ^ (px & 7)) << 4);
            if ((unsigned)hr < (unsigned)HH && (unsigned)gpx < (unsigned)WW)
                cpa16(su + doff, basep + ((size_t)((b * HH + hr) * WW + gpx)) * 128 + c * 64 + chunk * 8);
            else
                *reinterpret_cast<uint4*>(sm + doff) = make_uint4(0, 0, 0, 0);
        }
        cpa_commit();
    };
    auto stage_B2 = [&](int plane, int c, int slot) {            // x row h, CIN=256, no halo
        const h16* basep = plane ? xlo : xhi;
        for (int u = tid; u < 128 * 8; u += 256) {
            int chunk = u & 7, px = u >> 3;
            uint32_t doff = slot * SLOT + plane * BPL + px * 128 + ((chunk ^ (px & 7)) << 4);
            cpa16(su + doff, basep + ((size_t)((b * HH + h) * WW + px)) * 256 + c * 64 + chunk * 8);
        }
        cpa_commit();
    };

    auto compute = [&](uint32_t Ab, uint32_t bhB, uint32_t blB, int sp0) {
#pragma unroll
        for (int k = 0; k < 4; k++) {
            uint32_t ah[4][4];
#pragma unroll
            for (int mt = 0; mt < 4; mt++) {
                int row = mo + mt * 16 + (lane & 15);
                int ck  = k * 2 + (lane >> 4);
                ldsm4(Ab + row * 128 + ((ck ^ (row & 7)) << 4), ah[mt]);
            }
#pragma unroll
            for (int np = 0; np < 2; np++) {
                uint32_t bh[4], bl[4];
                int px = sp0 + np * 16 + (lane & 7) + ((lane >> 4) << 3);
                int ck = k * 2 + ((lane >> 3) & 1);
                uint32_t off = px * 128 + ((ck ^ (px & 7)) << 4);
                ldsm4(bhB + off, bh);
                ldsm4(blB + off, bl);
#pragma unroll
                for (int mt = 0; mt < 4; mt++)
#pragma unroll
                    for (int sb = 0; sb < 2; sb++) {
                        float* cc = acc[mt][np * 2 + sb];
                        mma16816(cc, ah[mt], bh[sb * 2], bh[sb * 2 + 1]);
                        mma16816(cc, ah[mt], bl[sb * 2], bl[sb * 2 + 1]);
                    }
            }
        }
    };

    stage_Brow(0, 0, 0, 0); stage_Brow(1, 0, 0, 0);
    stage_Brow(0, 0, 1, 1); stage_Brow(1, 0, 1, 1);
    stage_A(0, 0);
    cpa_wait0(); __syncthreads();

    int seq = 0;
    for (int gq = 0; gq < NG1; gq++) {
        const int slot = gq & 3;
        const uint32_t bhB = su + slot * SLOT, blB = bhB + BPL;
        const int ng = gq + 2;
#pragma unroll 1
        for (int sl = 0; sl < 3; sl++, seq++) {
            stage_A(seq + 1, (seq + 1) & 1);
            if (ng < NG1 && sl < 2) stage_Brow(sl, ng / 3, ng % 3, ng & 3);
            if (gq == NG1 - 1 && sl < 2) stage_B2(sl, 0, 2);     // prefetch c2 chunk0
            compute(su + ABASE + (seq & 1) * ABUF, bhB, blB, warpN * 32 + sl);
            cpa_wait0(); __syncthreads();
        }
    }
    // phase 2: c2 over x (4 chunks)
    for (int c2 = 0; c2 < 4; c2++) {
        const int slot = (c2 + 2) & 3;
        const int sq = 18 + c2;
        if (sq + 1 < 22) stage_A(sq + 1, (sq + 1) & 1);
        if (c2 + 1 < 4) { stage_B2(0, c2 + 1, (c2 + 3) & 3); stage_B2(1, c2 + 1, (c2 + 3) & 3); }
        compute(su + ABASE + (sq & 1) * ABUF, su + slot * SLOT, su + slot * SLOT + BPL, warpN * 32);
        cpa_wait0(); __syncthreads();
    }

    const int g = lane >> 2, q = lane & 3;
#pragma unroll
    for (int mt = 0; mt < 4; mt++)
#pragma unroll
        for (int half = 0; half < 2; half++) {
            const int co = co0 + mo + mt * 16 + g + half * 8;
            const float bi = b1[co] + b2[co];
            const size_t rowb = ((size_t)(b * COUT + co) * HH + h) * WW;
#pragma unroll
            for (int nt = 0; nt < 4; nt++) {
                const int px = warpN * 32 + nt * 8 + q * 2;
                float v0 = fmaxf(acc[mt][nt][half * 2 + 0] + bi, 0.f);
                float v1 = fmaxf(acc[mt][nt][half * 2 + 1] + bi, 0.f);
                *reinterpret_cast<float2*>(out + rowb + px) = make_float2(v0, v1);
            }
        }
}

// ------------------------- scans (exact, f32 NCHW) -------------------------
__global__ void colscan_kernel(float* __restrict__ p)
{
    int idx = blockIdx.x * blockDim.x + threadIdx.x;
    if (idx >= B_ * MID * WW) return;
    int w = idx % WW, bc = idx / WW;
    float* col = p + (size_t)bc * HW + w;
    float m = col[(HH - 1) * WW];
#pragma unroll 4
    for (int h = HH - 2; h >= 0; h--) {
        m = fmaxf(m, col[h * WW]);
        col[h * WW] = m;
    }
}
__global__ void rowscan_add_kernel(const float* __restrict__ p2, float* __restrict__ s)
{
    __shared__ float sm[WW];
    const int t = threadIdx.x;
    const size_t base = (size_t)blockIdx.x * WW;
    sm[t] = p2[base + t];
    __syncthreads();
#pragma unroll
    for (int off = 1; off < WW; off <<= 1) {
        float nv = sm[t];
        if (t + off < WW) nv = fmaxf(nv, sm[t + off]);
        __syncthreads();
        sm[t] = nv;
        __syncthreads();
    }
    s[base + t] += sm[t];
}

// ------------------------- launch -------------------------
extern "C" void kernel_launch(void* const* d_in, const int* in_sizes, int n_in,
                              void* d_out, int out_size)
{
    (void)in_sizes; (void)n_in; (void)out_size;

    const float* x = (const float*)d_in[0];

    float *p1, *p2, *t1, *sc, *bi;
    h16 *xh, *xl, *sh, *sl, *rh, *rl, *wp;
    cudaGetSymbolAddress((void**)&p1, g_p1);
    cudaGetSymbolAddress((void**)&p2, g_p2);
    cudaGetSymbolAddress((void**)&t1, g_t1);
    cudaGetSymbolAddress((void**)&sc, g_scale);
    cudaGetSymbolAddress((void**)&bi, g_bias);
    cudaGetSymbolAddress((void**)&xh, g_xT_hi);
    cudaGetSymbolAddress((void**)&xl, g_xT_lo);
    cudaGetSymbolAddress((void**)&sh, g_sT_hi);
    cudaGetSymbolAddress((void**)&sl, g_sT_lo);
    cudaGetSymbolAddress((void**)&rh, g_rT_hi);
    cudaGetSymbolAddress((void**)&rl, g_rT_lo);
    cudaGetSymbolAddress((void**)&wp, g_w);

    constexpr int SM3 = 4 * (2 * 130 * 128) + 2 * 16384;   // 165888
    cudaFuncSetAttribute(conv3<true>,  cudaFuncAttributeMaxDynamicSharedMemorySize, SM3);
    cudaFuncSetAttribute(conv3<false>, cudaFuncAttributeMaxDynamicSharedMemorySize, SM3);
    cudaFuncSetAttribute(conv_c1c2,    cudaFuncAttributeMaxDynamicSharedMemorySize, SM3);

    // merged BN folding + weight split
    P5 gg = {{(const float*)d_in[2],  (const float*)d_in[7],  (const float*)d_in[12], (const float*)d_in[17], (const float*)d_in[22]}};
    P5 bb = {{(const float*)d_in[3],  (const float*)d_in[8],  (const float*)d_in[13], (const float*)d_in[18], (const float*)d_in[23]}};
    P5 mm = {{(const float*)d_in[4],  (const float*)d_in[9],  (const float*)d_in[14], (const float*)d_in[19], (const float*)d_in[24]}};
    P5 vv = {{(const float*)d_in[5],  (const float*)d_in[10], (const float*)d_in[15], (const float*)d_in[20], (const float*)d_in[25]}};
    P5 ww = {{(const float*)d_in[1],  (const float*)d_in[6],  (const float*)d_in[11], (const float*)d_in[16], (const float*)d_in[21]}};
    bn_prep_all<<<4, 256>>>(gg, bb, mm, vv, sc, bi);
    wsplit_all<<<896, 256>>>(ww, sc, wp);

    // x -> NHWC fp16 hi/lo
    split_T<<<dim3(HW / 32, DIM / 32, B_), 256>>>(x, xh, xl, DIM);

    // p1 + p2 in one launch (grid.y selects branch)
    conv3<true><<<dim3(B_ * HH, 2), 256, SM3>>>(
        xh, xl, wp + WOFF_P1, wp + WOFF_P2, bi + 0, bi + 128, p1, p2, MID);

    // corner pooling: p1 <- revcummax_H(p1) + revcummax_W(p2)
    colscan_kernel<<<(B_ * MID * WW + 255) / 256, 256>>>(p1);
    rowscan_add_kernel<<<B_ * MID * HH, WW>>>(p2, p1);

    // s -> NHWC fp16 hi/lo
    split_T<<<dim3(HW / 32, MID / 32, B_), 256>>>(p1, sh, sl, MID);

    // fused c1 + c2 -> r (in t1)
    conv_c1c2<<<dim3(B_ * HH, 2), 256, SM3>>>(
        sh, sl, xh, xl, wp + WOFF_C1, wp + WOFF_C2, bi + 256, bi + 512, t1);

    // r -> NHWC fp16 hi/lo; p3
    split_T<<<dim3(HW / 32, DIM / 32, B_), 256>>>(t1, rh, rl, DIM);
    conv3<false><<<dim3(B_ * HH, 2), 256, SM3>>>(
        rh, rl, wp + WOFF_P3, nullptr, bi + 768, nullptr, (float*)d_out, nullptr, DIM);
}